// round 2
// baseline (speedup 1.0000x reference)
#include <cuda_runtime.h>
#include <cuda_bf16.h>
#include <math.h>

// ---------------------------------------------------------------------------
// Problem constants
// ---------------------------------------------------------------------------
#define BB   2
#define SS   512
#define DD   1024
#define NL   4
#define DFF  2048
#define HEADS 16
#define DK   64
#define MT   (BB*SS)          // 1024 token rows
#define VQN  768
#define VQD  64
#define NROWS_VQ (BB*DD*(SS/VQD))   // 16384
#define LN_EPS 1e-6f

// ---------------------------------------------------------------------------
// Scratch (static device globals; no allocation anywhere)
// ---------------------------------------------------------------------------
__device__ float g_x     [MT*DD];
__device__ float g_x2    [MT*DD];
__device__ float g_qkv   [3*MT*DD];
__device__ float g_attno [MT*DD];
__device__ float g_ffh   [MT*DFF];
__device__ float g_scores[BB*HEADS*SS*SS];
__device__ float g_eout  [MT*DD];
__device__ float g_vq    [MT*DD];
__device__ float g_embn  [VQN];
__device__ float g_rowloss[NROWS_VQ];

// ---------------------------------------------------------------------------
// Packed f32x2 helpers (Blackwell sm_103a packed fp32 pipe; ptxas never emits
// FFMA2 from C++ — only reachable via PTX fma.rn.f32x2)
// ---------------------------------------------------------------------------
__device__ __forceinline__ void fma2(unsigned long long& d,
                                     unsigned long long a,
                                     unsigned long long b) {
    asm("fma.rn.f32x2 %0, %1, %2, %0;" : "+l"(d) : "l"(a), "l"(b));
}
__device__ __forceinline__ unsigned long long pack_dup(float x) {
    unsigned long long r; unsigned int u = __float_as_uint(x);
    asm("mov.b64 %0, {%1, %1};" : "=l"(r) : "r"(u));
    return r;
}
__device__ __forceinline__ void unpack2(float& lo, float& hi, unsigned long long v) {
    asm("mov.b64 {%0, %1}, %2;" : "=f"(lo), "=f"(hi) : "l"(v));
}

// ---------------------------------------------------------------------------
// Block reduce helper
// ---------------------------------------------------------------------------
__device__ __forceinline__ float blockReduceSum(float v) {
    __shared__ float sh[32];
    int lane = threadIdx.x & 31;
    int wid  = threadIdx.x >> 5;
    #pragma unroll
    for (int o = 16; o; o >>= 1) v += __shfl_down_sync(0xffffffffu, v, o);
    if (lane == 0) sh[wid] = v;
    __syncthreads();
    int nw = blockDim.x >> 5;
    v = (threadIdx.x < nw) ? sh[threadIdx.x] : 0.f;
    if (wid == 0) {
        #pragma unroll
        for (int o = 16; o; o >>= 1) v += __shfl_down_sync(0xffffffffu, v, o);
        if (lane == 0) sh[0] = v;
    }
    __syncthreads();
    float r = sh[0];
    __syncthreads();
    return r;
}

// ---------------------------------------------------------------------------
// Generic batched GEMM: C = epilogue(alpha * A @ op(B))
//   A: M x K row-major (lda). B: NN -> K x N (ldb), NT -> N x K (ldb).
//   Batch z: offsets via zb=z/Hdim, zh=z%Hdim with separate strides.
//   Epilogue: +bias[n] (per-z stride), ReLU, +residual (same layout as C).
//   Requires: M % 128 == 0, K % 8 == 0, N % 8 == 0 (N may be < 128).
//   Inner product uses packed fma.rn.f32x2 (2 fp32 FMA / instr).
// ---------------------------------------------------------------------------
template<bool TB>
__global__ __launch_bounds__(256)
void gemm_k(const float* __restrict__ A, const float* __restrict__ B,
            const float* __restrict__ bias, const float* __restrict__ res,
            float* __restrict__ C,
            int M, int N, int K, int lda, int ldb, int ldc,
            int Hdim,
            long sAb, long sAh, long sBb, long sBh,
            long sCb, long sCh, long sBias,
            float alpha, int relu)
{
    int z  = blockIdx.z;
    int zb = z / Hdim, zh = z - zb * Hdim;
    A += zb * sAb + zh * sAh;
    B += zb * sBb + zh * sBh;
    long coff = zb * sCb + zh * sCh;
    C += coff;
    if (res)  res  += coff;
    if (bias) bias += (long)z * sBias;

    __shared__ float As[8][128];
    __shared__ float Bs[8][128];

    const int t  = threadIdx.x;
    const int bm = blockIdx.y * 128;
    const int bn = blockIdx.x * 128;

    // acc2[i][j] holds columns (2j, 2j+1) of output row i, packed f32x2
    unsigned long long acc2[8][4];
    #pragma unroll
    for (int i = 0; i < 8; i++)
        #pragma unroll
        for (int j = 0; j < 4; j++) acc2[i][j] = 0ull;   // {0.0f, 0.0f}

    const int a_m = t >> 1;
    const int a_k = (t & 1) << 2;
    const int tx  = t & 15;
    const int ty  = t >> 4;

    for (int k0 = 0; k0 < K; k0 += 8) {
        // A tile -> As[k][m]
        float4 av = *(const float4*)(A + (long)(bm + a_m) * lda + k0 + a_k);
        As[a_k + 0][a_m] = av.x;
        As[a_k + 1][a_m] = av.y;
        As[a_k + 2][a_m] = av.z;
        As[a_k + 3][a_m] = av.w;

        if (TB) {
            int n  = t >> 1;
            int k4 = (t & 1) << 2;
            float4 bv = make_float4(0.f, 0.f, 0.f, 0.f);
            if (bn + n < N)
                bv = *(const float4*)(B + (long)(bn + n) * ldb + k0 + k4);
            Bs[k4 + 0][n] = bv.x;
            Bs[k4 + 1][n] = bv.y;
            Bs[k4 + 2][n] = bv.z;
            Bs[k4 + 3][n] = bv.w;
        } else {
            int kk = t >> 5;
            int n4 = (t & 31) << 2;
            float4 bv = make_float4(0.f, 0.f, 0.f, 0.f);
            if (bn + n4 < N)
                bv = *(const float4*)(B + (long)(k0 + kk) * ldb + bn + n4);
            *(float4*)&Bs[kk][n4] = bv;
        }
        __syncthreads();

        #pragma unroll
        for (int kk = 0; kk < 8; kk++) {
            float ra[8];
            *(float4*)&ra[0] = *(const float4*)&As[kk][ty * 8];
            *(float4*)&ra[4] = *(const float4*)&As[kk][ty * 8 + 4];
            // B fragment: 8 consecutive floats = 4 packed f32x2 operands
            unsigned long long rb2[4];
            {
                ulonglong2 t0 = *(const ulonglong2*)&Bs[kk][tx * 8];
                ulonglong2 t1 = *(const ulonglong2*)&Bs[kk][tx * 8 + 4];
                rb2[0] = t0.x; rb2[1] = t0.y; rb2[2] = t1.x; rb2[3] = t1.y;
            }
            #pragma unroll
            for (int i = 0; i < 8; i++) {
                unsigned long long a2 = pack_dup(ra[i]);
                #pragma unroll
                for (int j = 0; j < 4; j++)
                    fma2(acc2[i][j], a2, rb2[j]);
            }
        }
        __syncthreads();
    }

    const int m0 = bm + ty * 8;
    const int n0 = bn + tx * 8;
    if (n0 < N) {
        #pragma unroll
        for (int i = 0; i < 8; i++) {
            float av[8];
            #pragma unroll
            for (int j = 0; j < 4; j++) unpack2(av[2*j], av[2*j+1], acc2[i][j]);
            #pragma unroll
            for (int j = 0; j < 8; j++) {
                float v = alpha * av[j];
                if (bias) v += bias[n0 + j];
                if (relu) v = fmaxf(v, 0.f);
                if (res)  v += res[(long)(m0 + i) * ldc + n0 + j];
                C[(long)(m0 + i) * ldc + n0 + j] = v;
            }
        }
    }
}

// ---------------------------------------------------------------------------
// LayerNorm: y = alpha[d]*(x-mean)/(std_unbiased + eps) + beta[d]
// ab = [alpha(D) | beta(D)], one block (256 thr) per row, D=1024.
// ---------------------------------------------------------------------------
__global__ __launch_bounds__(256)
void ln_k(const float* __restrict__ x, const float* __restrict__ ab,
          float* __restrict__ y)
{
    long row = blockIdx.x;
    const float* xr = x + row * DD;
    float v[4]; float s = 0.f;
    #pragma unroll
    for (int i = 0; i < 4; i++) { v[i] = xr[threadIdx.x + i * 256]; s += v[i]; }
    float mean = blockReduceSum(s) * (1.0f / DD);
    float s2 = 0.f;
    #pragma unroll
    for (int i = 0; i < 4; i++) { float d = v[i] - mean; s2 += d * d; }
    float var = blockReduceSum(s2) * (1.0f / (DD - 1));
    float inv = 1.0f / (sqrtf(var) + LN_EPS);
    #pragma unroll
    for (int i = 0; i < 4; i++) {
        int d = threadIdx.x + i * 256;
        y[row * DD + d] = ab[d] * (v[i] - mean) * inv + ab[DD + d];
    }
}

// ---------------------------------------------------------------------------
// Row softmax over 512 elements, one warp per row.
// ---------------------------------------------------------------------------
__global__ __launch_bounds__(256)
void softmax_k(float* __restrict__ s, int rows)
{
    int gw   = (blockIdx.x * blockDim.x + threadIdx.x) >> 5;
    int lane = threadIdx.x & 31;
    if (gw >= rows) return;
    float* r = s + (long)gw * SS;
    float v[16]; float mx = -3.4e38f;
    #pragma unroll
    for (int i = 0; i < 16; i++) { v[i] = r[lane + (i << 5)]; mx = fmaxf(mx, v[i]); }
    #pragma unroll
    for (int o = 16; o; o >>= 1) mx = fmaxf(mx, __shfl_xor_sync(0xffffffffu, mx, o));
    float sum = 0.f;
    #pragma unroll
    for (int i = 0; i < 16; i++) { v[i] = expf(v[i] - mx); sum += v[i]; }
    #pragma unroll
    for (int o = 16; o; o >>= 1) sum += __shfl_xor_sync(0xffffffffu, sum, o);
    float inv = 1.0f / sum;
    #pragma unroll
    for (int i = 0; i < 16; i++) r[lane + (i << 5)] = v[i] * inv;
}

// ---------------------------------------------------------------------------
// VQ codebook squared norms: one 64-thread block per code.
// ---------------------------------------------------------------------------
__global__ void embn_k(const float* __restrict__ emb, float* __restrict__ embn)
{
    int c = blockIdx.x;
    float e = emb[c * VQD + threadIdx.x];
    float s = e * e;
    #pragma unroll
    for (int o = 16; o; o >>= 1) s += __shfl_down_sync(0xffffffffu, s, o);
    __shared__ float sh[2];
    if ((threadIdx.x & 31) == 0) sh[threadIdx.x >> 5] = s;
    __syncthreads();
    if (threadIdx.x == 0) embn[c] = sh[0] + sh[1];
}

// ---------------------------------------------------------------------------
// VQ: one 128-thread block per row r = (b*D + d)*(S/64) + sb.
// Vector v[j] = eout[b, sb*64+j, d]. argmin_c (||e_c||^2 - 2 v.e_c),
// first-index tie-break. Writes quantized row + per-row commit-loss partial.
// ---------------------------------------------------------------------------
__global__ __launch_bounds__(128)
void vq_k(const float* __restrict__ eout, const float* __restrict__ emb,
          const float* __restrict__ embn, float* __restrict__ vq,
          float* __restrict__ rowloss)
{
    int r  = blockIdx.x;
    int sb = r & 7;                 // S/64 = 8
    int d  = (r >> 3) & (DD - 1);
    int b  = r >> 13;               // / (1024*8)
    __shared__ float v[VQD];
    __shared__ float sd[128];
    __shared__ int   si[128];
    int t = threadIdx.x;

    if (t < VQD)
        v[t] = eout[((long)(b * SS + sb * VQD + t)) * DD + d];
    __syncthreads();

    float bd = 3.4e38f; int bi = 0x7fffffff;
    for (int c = t; c < VQN; c += 128) {
        const float* e = emb + c * VQD;
        float dot = 0.f;
        #pragma unroll
        for (int j = 0; j < VQD; j++) dot = fmaf(e[j], v[j], dot);
        float dist = embn[c] - 2.0f * dot;
        if (dist < bd) { bd = dist; bi = c; }
    }
    sd[t] = bd; si[t] = bi;
    __syncthreads();
    #pragma unroll
    for (int s = 64; s; s >>= 1) {
        if (t < s) {
            float d2 = sd[t + s]; int i2 = si[t + s];
            if (d2 < sd[t] || (d2 == sd[t] && i2 < si[t])) { sd[t] = d2; si[t] = i2; }
        }
        __syncthreads();
    }
    int best = si[0];

    float part = 0.f;
    if (t < VQD) {
        float q  = emb[best * VQD + t];
        vq[((long)(b * SS + sb * VQD + t)) * DD + d] = q;
        float df = q - v[t];
        part = df * df;
    }
    float rs = blockReduceSum(part);
    if (t == 0) rowloss[r] = rs;
}

__global__ __launch_bounds__(256)
void lossred_k(const float* __restrict__ rl, float* __restrict__ out)
{
    float s = 0.f;
    for (int i = threadIdx.x; i < NROWS_VQ; i += 256) s += rl[i];
    s = blockReduceSum(s);
    if (threadIdx.x == 0) *out = 0.25f * s * (1.0f / (float)(MT * DD));
}

// ---------------------------------------------------------------------------
// Host-side launch helpers (default stream, graph-capturable)
// ---------------------------------------------------------------------------
static void gemm(const float* A, const float* B, const float* bias,
                 const float* res, float* C,
                 int M, int N, int K, int lda, int ldb, int ldc,
                 bool tb, int batch, int Hdim,
                 long sAb, long sAh, long sBb, long sBh,
                 long sCb, long sCh, long sBias,
                 float alpha, bool relu)
{
    dim3 grid((N + 127) / 128, M / 128, batch);
    dim3 blk(256);
    if (tb)
        gemm_k<true><<<grid, blk>>>(A, B, bias, res, C, M, N, K, lda, ldb, ldc,
                                    Hdim, sAb, sAh, sBb, sBh, sCb, sCh, sBias,
                                    alpha, relu ? 1 : 0);
    else
        gemm_k<false><<<grid, blk>>>(A, B, bias, res, C, M, N, K, lda, ldb, ldc,
                                     Hdim, sAb, sAh, sBb, sBh, sCb, sCh, sBias,
                                     alpha, relu ? 1 : 0);
}

// Self/cross attention core: qkv -> attno (scores scratch in g_scores).
static void attention(float* qkv, float* scores, float* attno)
{
    const long SD = (long)SS * DD;
    const long SSQ = (long)SS * SS;
    // scores[bh] = Q_bh @ K_bh^T / 8
    gemm(qkv, qkv + (long)MT * DD, nullptr, nullptr, scores,
         SS, SS, DK, DD, DD, SS,
         true, BB * HEADS, HEADS,
         SD, DK, SD, DK,
         (long)HEADS * SSQ, SSQ, 0,
         0.125f, false);
    int rows = BB * HEADS * SS;
    softmax_k<<<(rows * 32 + 255) / 256, 256>>>(scores, rows);
    // attno[bh] = P @ V_bh
    gemm(scores, qkv + 2L * MT * DD, nullptr, nullptr, attno,
         SS, DK, SS, SS, DD, DD,
         false, BB * HEADS, HEADS,
         (long)HEADS * SSQ, SSQ, SD, DK,
         SD, DK, 0,
         1.0f, false);
}

extern "C" void kernel_launch(void* const* d_in, const int* in_sizes, int n_in,
                              void* d_out, int out_size)
{
    const float* src       = (const float*)d_in[0];
    const float* trg       = (const float*)d_in[1];
    const float* enc_ln    = (const float*)d_in[2];
    const float* enc_aw    = (const float*)d_in[3];
    const float* enc_ab    = (const float*)d_in[4];
    const float* enc_w1    = (const float*)d_in[5];
    const float* enc_b1    = (const float*)d_in[6];
    const float* enc_w2    = (const float*)d_in[7];
    const float* enc_b2    = (const float*)d_in[8];
    const float* enc_fnorm = (const float*)d_in[9];
    const float* dec_ln    = (const float*)d_in[10];
    const float* a1w       = (const float*)d_in[11];
    const float* a1b       = (const float*)d_in[12];
    const float* a2w       = (const float*)d_in[13];
    const float* a2b       = (const float*)d_in[14];
    const float* dw1       = (const float*)d_in[15];
    const float* db1       = (const float*)d_in[16];
    const float* dw2       = (const float*)d_in[17];
    const float* db2       = (const float*)d_in[18];
    const float* dec_fnorm = (const float*)d_in[19];
    const float* out_w     = (const float*)d_in[20];
    const float* out_b     = (const float*)d_in[21];
    const float* vq_emb    = (const float*)d_in[22];

    float *x, *x2, *qkv, *attno, *ffh, *scores, *eout, *vq, *embn, *rowloss;
    cudaGetSymbolAddress((void**)&x,       g_x);
    cudaGetSymbolAddress((void**)&x2,      g_x2);
    cudaGetSymbolAddress((void**)&qkv,     g_qkv);
    cudaGetSymbolAddress((void**)&attno,   g_attno);
    cudaGetSymbolAddress((void**)&ffh,     g_ffh);
    cudaGetSymbolAddress((void**)&scores,  g_scores);
    cudaGetSymbolAddress((void**)&eout,    g_eout);
    cudaGetSymbolAddress((void**)&vq,      g_vq);
    cudaGetSymbolAddress((void**)&embn,    g_embn);
    cudaGetSymbolAddress((void**)&rowloss, g_rowloss);

    const long DDL  = (long)DD * DD;
    const long MTD  = (long)MT * DD;

    // ---------------- Encoder ----------------
    cudaMemcpyAsync(x, src, MTD * sizeof(float), cudaMemcpyDeviceToDevice);
    for (int l = 0; l < NL; l++) {
        // self-attention block
        ln_k<<<MT, 256>>>(x, enc_ln + (long)((l * 2 + 0) * 2) * DD, x2);
        gemm(x2, enc_aw + (long)l * 4 * DDL, enc_ab + (long)l * 4 * DD, nullptr, qkv,
             MT, DD, DD, DD, DD, DD,
             false, 3, 1, 0, 0, DDL, 0, MTD, 0, DD, 1.0f, false);
        attention(qkv, scores, attno);
        gemm(attno, enc_aw + (long)l * 4 * DDL + 3 * DDL,
             enc_ab + (long)l * 4 * DD + 3 * DD, x, x,
             MT, DD, DD, DD, DD, DD,
             false, 1, 1, 0, 0, 0, 0, 0, 0, 0, 1.0f, false);
        // FF block
        ln_k<<<MT, 256>>>(x, enc_ln + (long)((l * 2 + 1) * 2) * DD, x2);
        gemm(x2, enc_w1 + (long)l * DD * DFF, enc_b1 + (long)l * DFF, nullptr, ffh,
             MT, DFF, DD, DD, DFF, DFF,
             false, 1, 1, 0, 0, 0, 0, 0, 0, 0, 1.0f, true);
        gemm(ffh, enc_w2 + (long)l * DFF * DD, enc_b2 + (long)l * DD, x, x,
             MT, DD, DFF, DFF, DD, DD,
             false, 1, 1, 0, 0, 0, 0, 0, 0, 0, 1.0f, false);
    }
    ln_k<<<MT, 256>>>(x, enc_fnorm, eout);

    // ---------------- VQ ----------------
    embn_k<<<VQN, 64>>>(vq_emb, embn);
    vq_k<<<NROWS_VQ, 128>>>(eout, vq_emb, embn, vq, rowloss);

    // ---------------- Decoder ----------------
    cudaMemcpyAsync(x, trg, MTD * sizeof(float), cudaMemcpyDeviceToDevice);
    for (int l = 0; l < NL; l++) {
        // self-attention
        ln_k<<<MT, 256>>>(x, dec_ln + (long)((l * 3 + 0) * 2) * DD, x2);
        gemm(x2, a1w + (long)l * 4 * DDL, a1b + (long)l * 4 * DD, nullptr, qkv,
             MT, DD, DD, DD, DD, DD,
             false, 3, 1, 0, 0, DDL, 0, MTD, 0, DD, 1.0f, false);
        attention(qkv, scores, attno);
        gemm(attno, a1w + (long)l * 4 * DDL + 3 * DDL,
             a1b + (long)l * 4 * DD + 3 * DD, x, x,
             MT, DD, DD, DD, DD, DD,
             false, 1, 1, 0, 0, 0, 0, 0, 0, 0, 1.0f, false);
        // cross-attention (K,V from vq_output)
        ln_k<<<MT, 256>>>(x, dec_ln + (long)((l * 3 + 1) * 2) * DD, x2);
        gemm(x2, a2w + (long)l * 4 * DDL, a2b + (long)l * 4 * DD, nullptr, qkv,
             MT, DD, DD, DD, DD, DD,
             false, 1, 1, 0, 0, 0, 0, 0, 0, 0, 1.0f, false);
        gemm(vq, a2w + (long)l * 4 * DDL + DDL, a2b + (long)l * 4 * DD + DD,
             nullptr, qkv + MTD,
             MT, DD, DD, DD, DD, DD,
             false, 2, 1, 0, 0, DDL, 0, MTD, 0, DD, 1.0f, false);
        attention(qkv, scores, attno);
        gemm(attno, a2w + (long)l * 4 * DDL + 3 * DDL,
             a2b + (long)l * 4 * DD + 3 * DD, x, x,
             MT, DD, DD, DD, DD, DD,
             false, 1, 1, 0, 0, 0, 0, 0, 0, 0, 1.0f, false);
        // FF
        ln_k<<<MT, 256>>>(x, dec_ln + (long)((l * 3 + 2) * 2) * DD, x2);
        gemm(x2, dw1 + (long)l * DD * DFF, db1 + (long)l * DFF, nullptr, ffh,
             MT, DFF, DD, DD, DFF, DFF,
             false, 1, 1, 0, 0, 0, 0, 0, 0, 0, 1.0f, true);
        gemm(ffh, dw2 + (long)l * DFF * DD, db2 + (long)l * DD, x, x,
             MT, DD, DFF, DFF, DD, DD,
             false, 1, 1, 0, 0, 0, 0, 0, 0, 0, 1.0f, false);
    }
    ln_k<<<MT, 256>>>(x, dec_fnorm, x2);

    // ---------------- Output head + packed outputs ----------------
    float* outp = (float*)d_out;
    gemm(x2, out_w, out_b, nullptr, outp,
         MT, DD, DD, DD, DD, DD,
         false, 1, 1, 0, 0, 0, 0, 0, 0, 0, 1.0f, false);

    const long M1 = MTD; // 1048576
    if ((long)out_size >= 3 * M1 + 1) {
        cudaMemcpyAsync(outp + M1,     eout, M1 * sizeof(float), cudaMemcpyDeviceToDevice);
        cudaMemcpyAsync(outp + 2 * M1, vq,   M1 * sizeof(float), cudaMemcpyDeviceToDevice);
        lossred_k<<<1, 256>>>(rowloss, outp + 3 * M1);
    }
}

// round 14
// speedup vs baseline: 1.3058x; 1.3058x over previous
#include <cuda_runtime.h>
#include <cuda_bf16.h>
#include <math.h>
#include <stdint.h>

// ---------------------------------------------------------------------------
// Problem constants
// ---------------------------------------------------------------------------
#define BB   2
#define SS   512
#define DD   1024
#define NL   4
#define DFF  2048
#define HEADS 16
#define DK   64
#define MT   (BB*SS)
#define VQN  768
#define VQD  64
#define NROWS_VQ (BB*DD*(SS/VQD))
#define LN_EPS 1e-6f

// ---------------------------------------------------------------------------
// Scratch
// ---------------------------------------------------------------------------
__device__ float g_x     [MT*DD];
__device__ float g_x2    [MT*DD];
__device__ float g_qkv   [3*MT*DD];
__device__ float g_attno [MT*DD];
__device__ float g_ffh   [MT*DFF];
__device__ float g_scores[BB*HEADS*SS*SS];
__device__ float g_eout  [MT*DD];
__device__ float g_vq    [MT*DD];
__device__ float g_embn  [VQN];
__device__ float g_rowloss[NROWS_VQ];

// ===========================================================================
// ENGINE 1: fp32 f32x2 SIMT GEMM (R2, passed at rel_err 9.0e-7) — encoder
// ===========================================================================
__device__ __forceinline__ void fma2(unsigned long long& d,
                                     unsigned long long a,
                                     unsigned long long b) {
    asm("fma.rn.f32x2 %0, %1, %2, %0;" : "+l"(d) : "l"(a), "l"(b));
}
__device__ __forceinline__ unsigned long long pack_dup(float x) {
    unsigned long long r; unsigned int u = __float_as_uint(x);
    asm("mov.b64 %0, {%1, %1};" : "=l"(r) : "r"(u));
    return r;
}
__device__ __forceinline__ void unpack2(float& lo, float& hi, unsigned long long v) {
    asm("mov.b64 {%0, %1}, %2;" : "=f"(lo), "=f"(hi) : "l"(v));
}

template<bool TB>
__global__ __launch_bounds__(256)
void gemm_f32(const float* __restrict__ A, const float* __restrict__ B,
              const float* __restrict__ bias, const float* __restrict__ res,
              float* __restrict__ C,
              int M, int N, int K, int lda, int ldb, int ldc,
              int Hdim,
              long sAb, long sAh, long sBb, long sBh,
              long sCb, long sCh, long sBias,
              float alpha, int relu)
{
    int z  = blockIdx.z;
    int zb = z / Hdim, zh = z - zb * Hdim;
    A += zb * sAb + zh * sAh;
    B += zb * sBb + zh * sBh;
    long coff = zb * sCb + zh * sCh;
    C += coff;
    if (res)  res  += coff;
    if (bias) bias += (long)z * sBias;

    __shared__ float As[8][128];
    __shared__ float Bs[8][128];

    const int t  = threadIdx.x;
    const int bm = blockIdx.y * 128;
    const int bn = blockIdx.x * 128;

    unsigned long long acc2[8][4];
    #pragma unroll
    for (int i = 0; i < 8; i++)
        #pragma unroll
        for (int j = 0; j < 4; j++) acc2[i][j] = 0ull;

    const int a_m = t >> 1;
    const int a_k = (t & 1) << 2;
    const int tx  = t & 15;
    const int ty  = t >> 4;

    for (int k0 = 0; k0 < K; k0 += 8) {
        float4 av = *(const float4*)(A + (long)(bm + a_m) * lda + k0 + a_k);
        As[a_k + 0][a_m] = av.x;
        As[a_k + 1][a_m] = av.y;
        As[a_k + 2][a_m] = av.z;
        As[a_k + 3][a_m] = av.w;

        if (TB) {
            int n  = t >> 1;
            int k4 = (t & 1) << 2;
            float4 bv = make_float4(0.f, 0.f, 0.f, 0.f);
            if (bn + n < N)
                bv = *(const float4*)(B + (long)(bn + n) * ldb + k0 + k4);
            Bs[k4 + 0][n] = bv.x;
            Bs[k4 + 1][n] = bv.y;
            Bs[k4 + 2][n] = bv.z;
            Bs[k4 + 3][n] = bv.w;
        } else {
            int kk = t >> 5;
            int n4 = (t & 31) << 2;
            float4 bv = make_float4(0.f, 0.f, 0.f, 0.f);
            if (bn + n4 < N)
                bv = *(const float4*)(B + (long)(k0 + kk) * ldb + bn + n4);
            *(float4*)&Bs[kk][n4] = bv;
        }
        __syncthreads();

        #pragma unroll
        for (int kk = 0; kk < 8; kk++) {
            float ra[8];
            *(float4*)&ra[0] = *(const float4*)&As[kk][ty * 8];
            *(float4*)&ra[4] = *(const float4*)&As[kk][ty * 8 + 4];
            unsigned long long rb2[4];
            {
                ulonglong2 t0 = *(const ulonglong2*)&Bs[kk][tx * 8];
                ulonglong2 t1 = *(const ulonglong2*)&Bs[kk][tx * 8 + 4];
                rb2[0] = t0.x; rb2[1] = t0.y; rb2[2] = t1.x; rb2[3] = t1.y;
            }
            #pragma unroll
            for (int i = 0; i < 8; i++) {
                unsigned long long a2 = pack_dup(ra[i]);
                #pragma unroll
                for (int j = 0; j < 4; j++)
                    fma2(acc2[i][j], a2, rb2[j]);
            }
        }
        __syncthreads();
    }

    const int m0 = bm + ty * 8;
    const int n0 = bn + tx * 8;
    if (n0 < N) {
        #pragma unroll
        for (int i = 0; i < 8; i++) {
            float av[8];
            #pragma unroll
            for (int j = 0; j < 4; j++) unpack2(av[2*j], av[2*j+1], acc2[i][j]);
            #pragma unroll
            for (int j = 0; j < 8; j++) {
                float v = alpha * av[j];
                if (bias) v += bias[n0 + j];
                if (relu) v = fmaxf(v, 0.f);
                if (res)  v += res[(long)(m0 + i) * ldc + n0 + j];
                C[(long)(m0 + i) * ldc + n0 + j] = v;
            }
        }
    }
}

// ===========================================================================
// ENGINE 2: HMMA bf16 hi/lo SPLIT=2 GEMM (R8, numerically validated) — decoder
// ===========================================================================
__device__ __forceinline__ unsigned long long pk4(__nv_bfloat16 a, __nv_bfloat16 b,
                                                  __nv_bfloat16 c, __nv_bfloat16 d) {
    __nv_bfloat162 p0; p0.x = a; p0.y = b;
    __nv_bfloat162 p1; p1.x = c; p1.y = d;
    uint32_t u0 = *(uint32_t*)&p0, u1 = *(uint32_t*)&p1;
    unsigned long long r;
    asm("mov.b64 %0, {%1, %2};" : "=l"(r) : "r"(u0), "r"(u1));
    return r;
}
__device__ __forceinline__ void mma16816(float* c, const uint32_t* a, const uint32_t* b) {
    asm("mma.sync.aligned.m16n8k16.row.col.f32.bf16.bf16.f32 "
        "{%0,%1,%2,%3},{%4,%5,%6,%7},{%8,%9},{%0,%1,%2,%3};"
        : "+f"(c[0]), "+f"(c[1]), "+f"(c[2]), "+f"(c[3])
        : "r"(a[0]), "r"(a[1]), "r"(a[2]), "r"(a[3]), "r"(b[0]), "r"(b[1]));
}
#define ROWB 80
__device__ __forceinline__ uint32_t lds32(const char* base, int row, int col) {
    return *(const uint32_t*)(base + row * ROWB + col * 2);
}

template<int NT, bool BNMAJOR>
__global__ __launch_bounds__(256)
void gemm_mma(const float* __restrict__ A, const float* __restrict__ B,
              const float* __restrict__ bias, const float* __restrict__ res,
              float* __restrict__ C,
              int K, int lda, int ldb, int ldc, int Hdim,
              long sAb, long sAh, long sBb, long sBh,
              long sCb, long sCh, long sBias,
              float alpha, int relu)
{
    extern __shared__ char smem[];
    char* Ahi = smem;
    char* Alo = smem + 10240;
    char* Bhi = smem + 20480;
    char* Blo = smem + 20480 + NT * ROWB;

    const int t = threadIdx.x, wid = t >> 5, lid = t & 31;
    const int g = lid >> 2, cc = lid & 3;

    constexpr int WM = (NT == 128) ? 2 : 4;
    constexpr int WN = 8 / WM;
    constexpr int MROWS = 128 / WM;
    constexpr int NCOLS = NT / WN;
    constexpr int MF = MROWS / 16;
    constexpr int NF = NCOLS / 8;

    const int wm_base = (wid / WN) * MROWS;
    const int wn_base = (wid % WN) * NCOLS;

    int z = blockIdx.z, zb = z / Hdim, zh = z - zb * Hdim;
    A += zb * sAb + zh * sAh;
    B += zb * sBb + zh * sBh;
    long coff = zb * sCb + zh * sCh;
    C += coff;
    if (res)  res  += coff;
    if (bias) bias += (long)z * sBias;

    const int bm = blockIdx.y * 128;
    const int bn = blockIdx.x * NT;

    float acc[MF][NF][4];
    #pragma unroll
    for (int i = 0; i < MF; i++)
        #pragma unroll
        for (int j = 0; j < NF; j++)
            #pragma unroll
            for (int q = 0; q < 4; q++) acc[i][j][q] = 0.f;

    const int NB = K >> 5;
    float4 aR[4], bR[4];

    auto ldg_blk = [&](int blk) {
        const int k0 = blk << 5;
        {
            int r = t >> 1, kq = (t & 1) << 4;
            const float4* p = (const float4*)(A + (long)(bm + r) * lda + k0 + kq);
            #pragma unroll
            for (int i = 0; i < 4; i++) aR[i] = p[i];
        }
        if (!BNMAJOR) {
            int r = t >> 1, kq = (t & 1) << 4;
            const float4* p = (const float4*)(B + (long)(bn + r) * ldb + k0 + kq);
            #pragma unroll
            for (int i = 0; i < 4; i++) bR[i] = p[i];
        } else {
            int k = t >> 3, nb0 = (t & 7) * (NT / 8);
            const float4* p = (const float4*)(B + (long)(k0 + k) * ldb + bn + nb0);
            #pragma unroll
            for (int i = 0; i < NT / 32; i++) bR[i] = p[i];
        }
    };

    auto sts_blk = [&]() {
        {
            int r = t >> 1, kq = (t & 1) << 4;
            #pragma unroll
            for (int i = 0; i < 4; i++) {
                float4 v = aR[i];
                __nv_bfloat16 h0 = __float2bfloat16(v.x), h1 = __float2bfloat16(v.y);
                __nv_bfloat16 h2 = __float2bfloat16(v.z), h3 = __float2bfloat16(v.w);
                __nv_bfloat16 l0 = __float2bfloat16(v.x - __bfloat162float(h0));
                __nv_bfloat16 l1 = __float2bfloat16(v.y - __bfloat162float(h1));
                __nv_bfloat16 l2 = __float2bfloat16(v.z - __bfloat162float(h2));
                __nv_bfloat16 l3 = __float2bfloat16(v.w - __bfloat162float(h3));
                uint32_t off = (uint32_t)(r * ROWB + (kq + 4 * i) * 2);
                *(unsigned long long*)(Ahi + off) = pk4(h0, h1, h2, h3);
                *(unsigned long long*)(Alo + off) = pk4(l0, l1, l2, l3);
            }
        }
        if (!BNMAJOR) {
            int r = t >> 1, kq = (t & 1) << 4;
            #pragma unroll
            for (int i = 0; i < 4; i++) {
                float4 v = bR[i];
                __nv_bfloat16 h0 = __float2bfloat16(v.x), h1 = __float2bfloat16(v.y);
                __nv_bfloat16 h2 = __float2bfloat16(v.z), h3 = __float2bfloat16(v.w);
                __nv_bfloat16 l0 = __float2bfloat16(v.x - __bfloat162float(h0));
                __nv_bfloat16 l1 = __float2bfloat16(v.y - __bfloat162float(h1));
                __nv_bfloat16 l2 = __float2bfloat16(v.z - __bfloat162float(h2));
                __nv_bfloat16 l3 = __float2bfloat16(v.w - __bfloat162float(h3));
                uint32_t off = (uint32_t)(r * ROWB + (kq + 4 * i) * 2);
                *(unsigned long long*)(Bhi + off) = pk4(h0, h1, h2, h3);
                *(unsigned long long*)(Blo + off) = pk4(l0, l1, l2, l3);
            }
        } else {
            int k = t >> 3, nb0 = (t & 7) * (NT / 8);
            #pragma unroll
            for (int i = 0; i < NT / 32; i++) {
                float vv[4] = {bR[i].x, bR[i].y, bR[i].z, bR[i].w};
                #pragma unroll
                for (int j = 0; j < 4; j++) {
                    int n = nb0 + 4 * i + j;
                    __nv_bfloat16 h = __float2bfloat16(vv[j]);
                    __nv_bfloat16 l = __float2bfloat16(vv[j] - __bfloat162float(h));
                    *(__nv_bfloat16*)(Bhi + n * ROWB + k * 2) = h;
                    *(__nv_bfloat16*)(Blo + n * ROWB + k * 2) = l;
                }
            }
        }
    };

    ldg_blk(0);
    for (int blk = 0; blk < NB; blk++) {
        sts_blk();
        __syncthreads();
        if (blk + 1 < NB) ldg_blk(blk + 1);

        #pragma unroll
        for (int ks = 0; ks < 32; ks += 16) {
            uint32_t ah[MF][4], al[MF][4], bh2[NF][2], bl2[NF][2];
            #pragma unroll
            for (int i = 0; i < MF; i++) {
                int r0 = wm_base + i * 16 + g;
                int c0 = ks + 2 * cc;
                ah[i][0] = lds32(Ahi, r0,     c0);
                ah[i][1] = lds32(Ahi, r0 + 8, c0);
                ah[i][2] = lds32(Ahi, r0,     c0 + 8);
                ah[i][3] = lds32(Ahi, r0 + 8, c0 + 8);
                al[i][0] = lds32(Alo, r0,     c0);
                al[i][1] = lds32(Alo, r0 + 8, c0);
                al[i][2] = lds32(Alo, r0,     c0 + 8);
                al[i][3] = lds32(Alo, r0 + 8, c0 + 8);
            }
            #pragma unroll
            for (int j = 0; j < NF; j++) {
                int n = wn_base + j * 8 + g;
                int c0 = ks + 2 * cc;
                bh2[j][0] = lds32(Bhi, n, c0);
                bh2[j][1] = lds32(Bhi, n, c0 + 8);
                bl2[j][0] = lds32(Blo, n, c0);
                bl2[j][1] = lds32(Blo, n, c0 + 8);
            }
            #pragma unroll
            for (int i = 0; i < MF; i++)
                #pragma unroll
                for (int j = 0; j < NF; j++) {
                    mma16816(acc[i][j], ah[i], bh2[j]);
                    mma16816(acc[i][j], ah[i], bl2[j]);
                    mma16816(acc[i][j], al[i], bh2[j]);
                }
        }
        __syncthreads();
    }

    #pragma unroll
    for (int i = 0; i < MF; i++) {
        #pragma unroll
        for (int j = 0; j < NF; j++) {
            int col = bn + wn_base + j * 8 + 2 * cc;
            #pragma unroll
            for (int h = 0; h < 2; h++) {
                int row = bm + wm_base + i * 16 + g + 8 * h;
                float2 v;
                v.x = alpha * acc[i][j][2 * h + 0];
                v.y = alpha * acc[i][j][2 * h + 1];
                if (bias) { v.x += bias[col]; v.y += bias[col + 1]; }
                if (relu) { v.x = fmaxf(v.x, 0.f); v.y = fmaxf(v.y, 0.f); }
                if (res) {
                    const float2 r2 = *(const float2*)(res + (long)row * ldc + col);
                    v.x += r2.x; v.y += r2.y;
                }
                *(float2*)(C + (long)row * ldc + col) = v;
            }
        }
    }
}

// ---------------------------------------------------------------------------
// Block reduce helper
// ---------------------------------------------------------------------------
__device__ __forceinline__ float blockReduceSum(float v) {
    __shared__ float sh[32];
    int lane = threadIdx.x & 31;
    int wid  = threadIdx.x >> 5;
    #pragma unroll
    for (int o = 16; o; o >>= 1) v += __shfl_down_sync(0xffffffffu, v, o);
    if (lane == 0) sh[wid] = v;
    __syncthreads();
    int nw = blockDim.x >> 5;
    v = (threadIdx.x < nw) ? sh[threadIdx.x] : 0.f;
    if (wid == 0) {
        #pragma unroll
        for (int o = 16; o; o >>= 1) v += __shfl_down_sync(0xffffffffu, v, o);
        if (lane == 0) sh[0] = v;
    }
    __syncthreads();
    float r = sh[0];
    __syncthreads();
    return r;
}

// ---------------------------------------------------------------------------
// LayerNorm
// ---------------------------------------------------------------------------
__global__ __launch_bounds__(256)
void ln_k(const float* __restrict__ x, const float* __restrict__ ab,
          float* __restrict__ y)
{
    long row = blockIdx.x;
    const float* xr = x + row * DD;
    float v[4]; float s = 0.f;
    #pragma unroll
    for (int i = 0; i < 4; i++) { v[i] = xr[threadIdx.x + i * 256]; s += v[i]; }
    float mean = blockReduceSum(s) * (1.0f / DD);
    float s2 = 0.f;
    #pragma unroll
    for (int i = 0; i < 4; i++) { float d = v[i] - mean; s2 += d * d; }
    float var = blockReduceSum(s2) * (1.0f / (DD - 1));
    float inv = 1.0f / (sqrtf(var) + LN_EPS);
    #pragma unroll
    for (int i = 0; i < 4; i++) {
        int d = threadIdx.x + i * 256;
        y[row * DD + d] = ab[d] * (v[i] - mean) * inv + ab[DD + d];
    }
}

// ---------------------------------------------------------------------------
// Row softmax (512 elems, warp per row)
// ---------------------------------------------------------------------------
__global__ __launch_bounds__(256)
void softmax_k(float* __restrict__ s, int rows)
{
    int gw   = (blockIdx.x * blockDim.x + threadIdx.x) >> 5;
    int lane = threadIdx.x & 31;
    if (gw >= rows) return;
    float* r = s + (long)gw * SS;
    float v[16]; float mx = -3.4e38f;
    #pragma unroll
    for (int i = 0; i < 16; i++) { v[i] = r[lane + (i << 5)]; mx = fmaxf(mx, v[i]); }
    #pragma unroll
    for (int o = 16; o; o >>= 1) mx = fmaxf(mx, __shfl_xor_sync(0xffffffffu, mx, o));
    float sum = 0.f;
    #pragma unroll
    for (int i = 0; i < 16; i++) { v[i] = expf(v[i] - mx); sum += v[i]; }
    #pragma unroll
    for (int o = 16; o; o >>= 1) sum += __shfl_xor_sync(0xffffffffu, sum, o);
    float inv = 1.0f / sum;
    #pragma unroll
    for (int i = 0; i < 16; i++) r[lane + (i << 5)] = v[i] * inv;
}

// ---------------------------------------------------------------------------
// VQ kernels
// ---------------------------------------------------------------------------
__global__ void embn_k(const float* __restrict__ emb, float* __restrict__ embn)
{
    int c = blockIdx.x;
    float e = emb[c * VQD + threadIdx.x];
    float s = e * e;
    #pragma unroll
    for (int o = 16; o; o >>= 1) s += __shfl_down_sync(0xffffffffu, s, o);
    __shared__ float sh[2];
    if ((threadIdx.x & 31) == 0) sh[threadIdx.x >> 5] = s;
    __syncthreads();
    if (threadIdx.x == 0) embn[c] = sh[0] + sh[1];
}

__global__ __launch_bounds__(128)
void vq_k(const float* __restrict__ eout, const float* __restrict__ emb,
          const float* __restrict__ embn, float* __restrict__ vq,
          float* __restrict__ rowloss)
{
    int r  = blockIdx.x;
    int sb = r & 7;
    int d  = (r >> 3) & (DD - 1);
    int b  = r >> 13;
    __shared__ float v[VQD];
    __shared__ float sd[128];
    __shared__ int   si[128];
    int t = threadIdx.x;

    if (t < VQD)
        v[t] = eout[((long)(b * SS + sb * VQD + t)) * DD + d];
    __syncthreads();

    float bd = 3.4e38f; int bi = 0x7fffffff;
    for (int c = t; c < VQN; c += 128) {
        const float* e = emb + c * VQD;
        float dot = 0.f;
        #pragma unroll
        for (int j = 0; j < VQD; j++) dot = fmaf(e[j], v[j], dot);
        float dist = embn[c] - 2.0f * dot;
        if (dist < bd) { bd = dist; bi = c; }
    }
    sd[t] = bd; si[t] = bi;
    __syncthreads();
    #pragma unroll
    for (int s = 64; s; s >>= 1) {
        if (t < s) {
            float d2 = sd[t + s]; int i2 = si[t + s];
            if (d2 < sd[t] || (d2 == sd[t] && i2 < si[t])) { sd[t] = d2; si[t] = i2; }
        }
        __syncthreads();
    }
    int best = si[0];

    float part = 0.f;
    if (t < VQD) {
        float q  = emb[best * VQD + t];
        vq[((long)(b * SS + sb * VQD + t)) * DD + d] = q;
        float df = q - v[t];
        part = df * df;
    }
    float rs = blockReduceSum(part);
    if (t == 0) rowloss[r] = rs;
}

__global__ __launch_bounds__(256)
void lossred_k(const float* __restrict__ rl, float* __restrict__ out)
{
    float s = 0.f;
    for (int i = threadIdx.x; i < NROWS_VQ; i += 256) s += rl[i];
    s = blockReduceSum(s);
    if (threadIdx.x == 0) *out = 0.25f * s * (1.0f / (float)(MT * DD));
}

// ---------------------------------------------------------------------------
// Host launch helpers
// ---------------------------------------------------------------------------
static void gemm32(const float* A, const float* B, const float* bias,
                   const float* res, float* C,
                   int M, int N, int K, int lda, int ldb, int ldc,
                   bool tb, int batch, int Hdim,
                   long sAb, long sAh, long sBb, long sBh,
                   long sCb, long sCh, long sBias,
                   float alpha, bool relu)
{
    dim3 grid((N + 127) / 128, M / 128, batch);
    if (tb)
        gemm_f32<true><<<grid, 256>>>(A, B, bias, res, C, M, N, K, lda, ldb, ldc,
                                      Hdim, sAb, sAh, sBb, sBh, sCb, sCh, sBias,
                                      alpha, relu ? 1 : 0);
    else
        gemm_f32<false><<<grid, 256>>>(A, B, bias, res, C, M, N, K, lda, ldb, ldc,
                                       Hdim, sAb, sAh, sBb, sBh, sCb, sCh, sBias,
                                       alpha, relu ? 1 : 0);
}

static void gemmMMA(const float* A, const float* B, const float* bias,
                    const float* res, float* C,
                    int M, int N, int K, int lda, int ldb, int ldc,
                    bool bnmajor, int batch, int Hdim,
                    long sAb, long sAh, long sBb, long sBh,
                    long sCb, long sCh, long sBias,
                    float alpha, bool relu)
{
    int NT = (N % 128 == 0) ? 128 : 64;
    dim3 grid(N / NT, M / 128, batch);
    size_t smem = 20480 + (size_t)NT * 160;   // <= 40960 B, under default limit
    int rl = relu ? 1 : 0;
    if (NT == 128) {
        if (bnmajor)
            gemm_mma<128, true><<<grid, 256, smem>>>(A, B, bias, res, C,
                K, lda, ldb, ldc, Hdim, sAb, sAh, sBb, sBh, sCb, sCh, sBias, alpha, rl);
        else
            gemm_mma<128, false><<<grid, 256, smem>>>(A, B, bias, res, C,
                K, lda, ldb, ldc, Hdim, sAb, sAh, sBb, sBh, sCb, sCh, sBias, alpha, rl);
    } else {
        gemm_mma<64, true><<<grid, 256, smem>>>(A, B, bias, res, C,
            K, lda, ldb, ldc, Hdim, sAb, sAh, sBb, sBh, sCb, sCh, sBias, alpha, rl);
    }
}

// Encoder attention: fp32 engine (R2 wiring, passed)
static void attention32(float* qkv, float* scores, float* attno)
{
    const long SD  = (long)SS * DD;
    const long SSQ = (long)SS * SS;
    gemm32(qkv, qkv + (long)MT * DD, nullptr, nullptr, scores,
           SS, SS, DK, DD, DD, SS,
           true, BB * HEADS, HEADS,
           SD, DK, SD, DK,
           (long)HEADS * SSQ, SSQ, 0,
           0.125f, false);
    int rows = BB * HEADS * SS;
    softmax_k<<<(rows * 32 + 255) / 256, 256>>>(scores, rows);
    gemm32(scores, qkv + 2L * MT * DD, nullptr, nullptr, attno,
           SS, DK, SS, SS, DD, DD,
           false, BB * HEADS, HEADS,
           (long)HEADS * SSQ, SSQ, SD, DK,
           SD, DK, 0,
           1.0f, false);
}

// Decoder attention: HMMA engine (R8 wiring, validated)
static void attentionMMA(float* qkv, float* scores, float* attno)
{
    const long SD  = (long)SS * DD;
    const long SSQ = (long)SS * SS;
    gemmMMA(qkv, qkv + (long)MT * DD, nullptr, nullptr, scores,
            SS, SS, DK, DD, DD, SS,
            false, BB * HEADS, HEADS,
            SD, DK, SD, DK,
            (long)HEADS * SSQ, SSQ, 0,
            0.125f, false);
    int rows = BB * HEADS * SS;
    softmax_k<<<(rows * 32 + 255) / 256, 256>>>(scores, rows);
    gemmMMA(scores, qkv + 2L * MT * DD, nullptr, nullptr, attno,
            SS, DK, SS, SS, DD, DD,
            true, BB * HEADS, HEADS,
            (long)HEADS * SSQ, SSQ, SD, DK,
            SD, DK, 0,
            1.0f, false);
}

extern "C" void kernel_launch(void* const* d_in, const int* in_sizes, int n_in,
                              void* d_out, int out_size)
{
    const float* src       = (const float*)d_in[0];
    const float* trg       = (const float*)d_in[1];
    const float* enc_ln    = (const float*)d_in[2];
    const float* enc_aw    = (const float*)d_in[3];
    const float* enc_ab    = (const float*)d_in[4];
    const float* enc_w1    = (const float*)d_in[5];
    const float* enc_b1    = (const float*)d_in[6];
    const float* enc_w2    = (const float*)d_in[7];
    const float* enc_b2    = (const float*)d_in[8];
    const float* enc_fnorm = (const float*)d_in[9];
    const float* dec_ln    = (const float*)d_in[10];
    const float* a1w       = (const float*)d_in[11];
    const float* a1b       = (const float*)d_in[12];
    const float* a2w       = (const float*)d_in[13];
    const float* a2b       = (const float*)d_in[14];
    const float* dw1       = (const float*)d_in[15];
    const float* db1       = (const float*)d_in[16];
    const float* dw2       = (const float*)d_in[17];
    const float* db2       = (const float*)d_in[18];
    const float* dec_fnorm = (const float*)d_in[19];
    const float* out_w     = (const float*)d_in[20];
    const float* out_b     = (const float*)d_in[21];
    const float* vq_emb    = (const float*)d_in[22];

    float *x, *x2, *qkv, *attno, *ffh, *scores, *eout, *vq, *embn, *rowloss;
    cudaGetSymbolAddress((void**)&x,       g_x);
    cudaGetSymbolAddress((void**)&x2,      g_x2);
    cudaGetSymbolAddress((void**)&qkv,     g_qkv);
    cudaGetSymbolAddress((void**)&attno,   g_attno);
    cudaGetSymbolAddress((void**)&ffh,     g_ffh);
    cudaGetSymbolAddress((void**)&scores,  g_scores);
    cudaGetSymbolAddress((void**)&eout,    g_eout);
    cudaGetSymbolAddress((void**)&vq,      g_vq);
    cudaGetSymbolAddress((void**)&embn,    g_embn);
    cudaGetSymbolAddress((void**)&rowloss, g_rowloss);

    const long DDL = (long)DD * DD;
    const long MTD = (long)MT * DD;

    // ---------------- Encoder: fp32 engine (feeds VQ argmin) ----------------
    cudaMemcpyAsync(x, src, MTD * sizeof(float), cudaMemcpyDeviceToDevice);
    for (int l = 0; l < NL; l++) {
        ln_k<<<MT, 256>>>(x, enc_ln + (long)((l * 2 + 0) * 2) * DD, x2);
        gemm32(x2, enc_aw + (long)l * 4 * DDL, enc_ab + (long)l * 4 * DD, nullptr, qkv,
               MT, DD, DD, DD, DD, DD,
               false, 3, 1, 0, 0, DDL, 0, MTD, 0, DD, 1.0f, false);
        attention32(qkv, scores, attno);
        gemm32(attno, enc_aw + (long)l * 4 * DDL + 3 * DDL,
               enc_ab + (long)l * 4 * DD + 3 * DD, x, x,
               MT, DD, DD, DD, DD, DD,
               false, 1, 1, 0, 0, 0, 0, 0, 0, 0, 1.0f, false);
        ln_k<<<MT, 256>>>(x, enc_ln + (long)((l * 2 + 1) * 2) * DD, x2);
        gemm32(x2, enc_w1 + (long)l * DD * DFF, enc_b1 + (long)l * DFF, nullptr, ffh,
               MT, DFF, DD, DD, DFF, DFF,
               false, 1, 1, 0, 0, 0, 0, 0, 0, 0, 1.0f, true);
        gemm32(ffh, enc_w2 + (long)l * DFF * DD, enc_b2 + (long)l * DD, x, x,
               MT, DD, DFF, DFF, DD, DD,
               false, 1, 1, 0, 0, 0, 0, 0, 0, 0, 1.0f, false);
    }
    ln_k<<<MT, 256>>>(x, enc_fnorm, eout);

    // ---------------- VQ ----------------
    embn_k<<<VQN, 64>>>(vq_emb, embn);
    vq_k<<<NROWS_VQ, 128>>>(eout, vq_emb, embn, vq, rowloss);

    // ---------------- Decoder: HMMA SPLIT=2 engine ----------------
    cudaMemcpyAsync(x, trg, MTD * sizeof(float), cudaMemcpyDeviceToDevice);
    for (int l = 0; l < NL; l++) {
        ln_k<<<MT, 256>>>(x, dec_ln + (long)((l * 3 + 0) * 2) * DD, x2);
        gemmMMA(x2, a1w + (long)l * 4 * DDL, a1b + (long)l * 4 * DD, nullptr, qkv,
                MT, DD, DD, DD, DD, DD,
                true, 3, 1, 0, 0, DDL, 0, MTD, 0, DD, 1.0f, false);
        attentionMMA(qkv, scores, attno);
        gemmMMA(attno, a1w + (long)l * 4 * DDL + 3 * DDL,
                a1b + (long)l * 4 * DD + 3 * DD, x, x,
                MT, DD, DD, DD, DD, DD,
                true, 1, 1, 0, 0, 0, 0, 0, 0, 0, 1.0f, false);
        ln_k<<<MT, 256>>>(x, dec_ln + (long)((l * 3 + 1) * 2) * DD, x2);
        gemmMMA(x2, a2w + (long)l * 4 * DDL, a2b + (long)l * 4 * DD, nullptr, qkv,
                MT, DD, DD, DD, DD, DD,
                true, 1, 1, 0, 0, 0, 0, 0, 0, 0, 1.0f, false);
        gemmMMA(vq, a2w + (long)l * 4 * DDL + DDL, a2b + (long)l * 4 * DD + DD,
                nullptr, qkv + MTD,
                MT, DD, DD, DD, DD, DD,
                true, 2, 1, 0, 0, DDL, 0, MTD, 0, DD, 1.0f, false);
        attentionMMA(qkv, scores, attno);
        gemmMMA(attno, a2w + (long)l * 4 * DDL + 3 * DDL,
                a2b + (long)l * 4 * DD + 3 * DD, x, x,
                MT, DD, DD, DD, DD, DD,
                true, 1, 1, 0, 0, 0, 0, 0, 0, 0, 1.0f, false);
        ln_k<<<MT, 256>>>(x, dec_ln + (long)((l * 3 + 2) * 2) * DD, x2);
        gemmMMA(x2, dw1 + (long)l * DD * DFF, db1 + (long)l * DFF, nullptr, ffh,
                MT, DFF, DD, DD, DFF, DFF,
                true, 1, 1, 0, 0, 0, 0, 0, 0, 0, 1.0f, true);
        gemmMMA(ffh, dw2 + (long)l * DFF * DD, db2 + (long)l * DD, x, x,
                MT, DD, DFF, DFF, DD, DD,
                true, 1, 1, 0, 0, 0, 0, 0, 0, 0, 1.0f, false);
    }
    ln_k<<<MT, 256>>>(x, dec_fnorm, x2);

    // ---------------- Output head (HMMA) + packed outputs ----------------
    float* outp = (float*)d_out;
    gemmMMA(x2, out_w, out_b, nullptr, outp,
            MT, DD, DD, DD, DD, DD,
            true, 1, 1, 0, 0, 0, 0, 0, 0, 0, 1.0f, false);

    const long M1 = MTD;
    if ((long)out_size >= 3 * M1 + 1) {
        cudaMemcpyAsync(outp + M1,     eout, M1 * sizeof(float), cudaMemcpyDeviceToDevice);
        cudaMemcpyAsync(outp + 2 * M1, vq,   M1 * sizeof(float), cudaMemcpyDeviceToDevice);
        lossred_k<<<1, 256>>>(rowloss, outp + 3 * M1);
    }
}

// round 15
// speedup vs baseline: 1.3112x; 1.0041x over previous
#include <cuda_runtime.h>
#include <cuda_bf16.h>
#include <math.h>
#include <stdint.h>

// ---------------------------------------------------------------------------
// Problem constants
// ---------------------------------------------------------------------------
#define BB   2
#define SS   512
#define DD   1024
#define NL   4
#define DFF  2048
#define HEADS 16
#define DK   64
#define MT   (BB*SS)
#define VQN  768
#define VQD  64
#define NROWS_VQ (BB*DD*(SS/VQD))
#define LN_EPS 1e-6f

// ---------------------------------------------------------------------------
// Scratch
// ---------------------------------------------------------------------------
__device__ float g_x     [MT*DD];
__device__ float g_x2    [MT*DD];
__device__ float g_qkv   [3*MT*DD];
__device__ float g_attno [MT*DD];
__device__ float g_ffh   [MT*DFF];
__device__ float g_scores[BB*HEADS*SS*SS];
__device__ float g_eout  [MT*DD];
__device__ float g_vq    [MT*DD];
__device__ float g_embn  [VQN];
__device__ float g_rowloss[NROWS_VQ];

// ===========================================================================
// ENGINE 1: fp32 f32x2 SIMT GEMM (R2 math, now double-buffered) — encoder
// ===========================================================================
__device__ __forceinline__ void fma2(unsigned long long& d,
                                     unsigned long long a,
                                     unsigned long long b) {
    asm("fma.rn.f32x2 %0, %1, %2, %0;" : "+l"(d) : "l"(a), "l"(b));
}
__device__ __forceinline__ unsigned long long pack_dup(float x) {
    unsigned long long r; unsigned int u = __float_as_uint(x);
    asm("mov.b64 %0, {%1, %1};" : "=l"(r) : "r"(u));
    return r;
}
__device__ __forceinline__ void unpack2(float& lo, float& hi, unsigned long long v) {
    asm("mov.b64 {%0, %1}, %2;" : "=f"(lo), "=f"(hi) : "l"(v));
}

template<bool TB>
__global__ __launch_bounds__(256)
void gemm_f32(const float* __restrict__ A, const float* __restrict__ B,
              const float* __restrict__ bias, const float* __restrict__ res,
              float* __restrict__ C,
              int M, int N, int K, int lda, int ldb, int ldc,
              int Hdim,
              long sAb, long sAh, long sBb, long sBh,
              long sCb, long sCh, long sBias,
              float alpha, int relu)
{
    int z  = blockIdx.z;
    int zb = z / Hdim, zh = z - zb * Hdim;
    A += zb * sAb + zh * sAh;
    B += zb * sBb + zh * sBh;
    long coff = zb * sCb + zh * sCh;
    C += coff;
    if (res)  res  += coff;
    if (bias) bias += (long)z * sBias;

    __shared__ float As[2][8][128];
    __shared__ float Bs[2][8][128];

    const int t  = threadIdx.x;
    const int bm = blockIdx.y * 128;
    const int bn = blockIdx.x * 128;

    unsigned long long acc2[8][4];
    #pragma unroll
    for (int i = 0; i < 8; i++)
        #pragma unroll
        for (int j = 0; j < 4; j++) acc2[i][j] = 0ull;

    const int a_m = t >> 1;
    const int a_k = (t & 1) << 2;
    const int tx  = t & 15;
    const int ty  = t >> 4;
    // B loader indices
    const int tb_n  = t >> 1;          // TB path: B row
    const int tb_k4 = (t & 1) << 2;    // TB path: k offset
    const int nn_kk = t >> 5;          // NN path: k row
    const int nn_n4 = (t & 31) << 2;   // NN path: n offset

    float4 avR, bvR;

    auto ldg = [&](int k0) {
        avR = *(const float4*)(A + (long)(bm + a_m) * lda + k0 + a_k);
        if (TB) {
            bvR = make_float4(0.f, 0.f, 0.f, 0.f);
            if (bn + tb_n < N)
                bvR = *(const float4*)(B + (long)(bn + tb_n) * ldb + k0 + tb_k4);
        } else {
            bvR = make_float4(0.f, 0.f, 0.f, 0.f);
            if (bn + nn_n4 < N)
                bvR = *(const float4*)(B + (long)(k0 + nn_kk) * ldb + bn + nn_n4);
        }
    };
    auto sts = [&](int p) {
        As[p][a_k + 0][a_m] = avR.x;
        As[p][a_k + 1][a_m] = avR.y;
        As[p][a_k + 2][a_m] = avR.z;
        As[p][a_k + 3][a_m] = avR.w;
        if (TB) {
            Bs[p][tb_k4 + 0][tb_n] = bvR.x;
            Bs[p][tb_k4 + 1][tb_n] = bvR.y;
            Bs[p][tb_k4 + 2][tb_n] = bvR.z;
            Bs[p][tb_k4 + 3][tb_n] = bvR.w;
        } else {
            *(float4*)&Bs[p][nn_kk][nn_n4] = bvR;
        }
    };

    const int nblk = K >> 3;
    ldg(0);
    sts(0);
    __syncthreads();

    for (int blk = 0; blk < nblk; blk++) {
        const int p = blk & 1;
        if (blk + 1 < nblk) ldg((blk + 1) << 3);

        #pragma unroll
        for (int kk = 0; kk < 8; kk++) {
            float ra[8];
            *(float4*)&ra[0] = *(const float4*)&As[p][kk][ty * 8];
            *(float4*)&ra[4] = *(const float4*)&As[p][kk][ty * 8 + 4];
            unsigned long long rb2[4];
            {
                ulonglong2 t0 = *(const ulonglong2*)&Bs[p][kk][tx * 8];
                ulonglong2 t1 = *(const ulonglong2*)&Bs[p][kk][tx * 8 + 4];
                rb2[0] = t0.x; rb2[1] = t0.y; rb2[2] = t1.x; rb2[3] = t1.y;
            }
            #pragma unroll
            for (int i = 0; i < 8; i++) {
                unsigned long long a2 = pack_dup(ra[i]);
                #pragma unroll
                for (int j = 0; j < 4; j++)
                    fma2(acc2[i][j], a2, rb2[j]);
            }
        }

        if (blk + 1 < nblk) sts(1 - p);
        __syncthreads();
    }

    const int m0 = bm + ty * 8;
    const int n0 = bn + tx * 8;
    if (n0 < N) {
        #pragma unroll
        for (int i = 0; i < 8; i++) {
            float av[8];
            #pragma unroll
            for (int j = 0; j < 4; j++) unpack2(av[2*j], av[2*j+1], acc2[i][j]);
            #pragma unroll
            for (int j = 0; j < 8; j++) {
                float v = alpha * av[j];
                if (bias) v += bias[n0 + j];
                if (relu) v = fmaxf(v, 0.f);
                if (res)  v += res[(long)(m0 + i) * ldc + n0 + j];
                C[(long)(m0 + i) * ldc + n0 + j] = v;
            }
        }
    }
}

// ===========================================================================
// ENGINE 2: HMMA bf16 hi/lo SPLIT=2 GEMM (R8/R14, passing) — decoder
// ===========================================================================
__device__ __forceinline__ unsigned long long pk4(__nv_bfloat16 a, __nv_bfloat16 b,
                                                  __nv_bfloat16 c, __nv_bfloat16 d) {
    __nv_bfloat162 p0; p0.x = a; p0.y = b;
    __nv_bfloat162 p1; p1.x = c; p1.y = d;
    uint32_t u0 = *(uint32_t*)&p0, u1 = *(uint32_t*)&p1;
    unsigned long long r;
    asm("mov.b64 %0, {%1, %2};" : "=l"(r) : "r"(u0), "r"(u1));
    return r;
}
__device__ __forceinline__ void mma16816(float* c, const uint32_t* a, const uint32_t* b) {
    asm("mma.sync.aligned.m16n8k16.row.col.f32.bf16.bf16.f32 "
        "{%0,%1,%2,%3},{%4,%5,%6,%7},{%8,%9},{%0,%1,%2,%3};"
        : "+f"(c[0]), "+f"(c[1]), "+f"(c[2]), "+f"(c[3])
        : "r"(a[0]), "r"(a[1]), "r"(a[2]), "r"(a[3]), "r"(b[0]), "r"(b[1]));
}
#define ROWB 80
__device__ __forceinline__ uint32_t lds32(const char* base, int row, int col) {
    return *(const uint32_t*)(base + row * ROWB + col * 2);
}

template<int NT, bool BNMAJOR>
__global__ __launch_bounds__(256)
void gemm_mma(const float* __restrict__ A, const float* __restrict__ B,
              const float* __restrict__ bias, const float* __restrict__ res,
              float* __restrict__ C,
              int K, int lda, int ldb, int ldc, int Hdim,
              long sAb, long sAh, long sBb, long sBh,
              long sCb, long sCh, long sBias,
              float alpha, int relu)
{
    extern __shared__ char smem[];
    char* Ahi = smem;
    char* Alo = smem + 10240;
    char* Bhi = smem + 20480;
    char* Blo = smem + 20480 + NT * ROWB;

    const int t = threadIdx.x, wid = t >> 5, lid = t & 31;
    const int g = lid >> 2, cc = lid & 3;

    constexpr int WM = (NT == 128) ? 2 : 4;
    constexpr int WN = 8 / WM;
    constexpr int MROWS = 128 / WM;
    constexpr int NCOLS = NT / WN;
    constexpr int MF = MROWS / 16;
    constexpr int NF = NCOLS / 8;

    const int wm_base = (wid / WN) * MROWS;
    const int wn_base = (wid % WN) * NCOLS;

    int z = blockIdx.z, zb = z / Hdim, zh = z - zb * Hdim;
    A += zb * sAb + zh * sAh;
    B += zb * sBb + zh * sBh;
    long coff = zb * sCb + zh * sCh;
    C += coff;
    if (res)  res  += coff;
    if (bias) bias += (long)z * sBias;

    const int bm = blockIdx.y * 128;
    const int bn = blockIdx.x * NT;

    float acc[MF][NF][4];
    #pragma unroll
    for (int i = 0; i < MF; i++)
        #pragma unroll
        for (int j = 0; j < NF; j++)
            #pragma unroll
            for (int q = 0; q < 4; q++) acc[i][j][q] = 0.f;

    const int NB = K >> 5;
    float4 aR[4], bR[4];

    auto ldg_blk = [&](int blk) {
        const int k0 = blk << 5;
        {
            int r = t >> 1, kq = (t & 1) << 4;
            const float4* p = (const float4*)(A + (long)(bm + r) * lda + k0 + kq);
            #pragma unroll
            for (int i = 0; i < 4; i++) aR[i] = p[i];
        }
        if (!BNMAJOR) {
            int r = t >> 1, kq = (t & 1) << 4;
            const float4* p = (const float4*)(B + (long)(bn + r) * ldb + k0 + kq);
            #pragma unroll
            for (int i = 0; i < 4; i++) bR[i] = p[i];
        } else {
            int k = t >> 3, nb0 = (t & 7) * (NT / 8);
            const float4* p = (const float4*)(B + (long)(k0 + k) * ldb + bn + nb0);
            #pragma unroll
            for (int i = 0; i < NT / 32; i++) bR[i] = p[i];
        }
    };

    auto sts_blk = [&]() {
        {
            int r = t >> 1, kq = (t & 1) << 4;
            #pragma unroll
            for (int i = 0; i < 4; i++) {
                float4 v = aR[i];
                __nv_bfloat16 h0 = __float2bfloat16(v.x), h1 = __float2bfloat16(v.y);
                __nv_bfloat16 h2 = __float2bfloat16(v.z), h3 = __float2bfloat16(v.w);
                __nv_bfloat16 l0 = __float2bfloat16(v.x - __bfloat162float(h0));
                __nv_bfloat16 l1 = __float2bfloat16(v.y - __bfloat162float(h1));
                __nv_bfloat16 l2 = __float2bfloat16(v.z - __bfloat162float(h2));
                __nv_bfloat16 l3 = __float2bfloat16(v.w - __bfloat162float(h3));
                uint32_t off = (uint32_t)(r * ROWB + (kq + 4 * i) * 2);
                *(unsigned long long*)(Ahi + off) = pk4(h0, h1, h2, h3);
                *(unsigned long long*)(Alo + off) = pk4(l0, l1, l2, l3);
            }
        }
        if (!BNMAJOR) {
            int r = t >> 1, kq = (t & 1) << 4;
            #pragma unroll
            for (int i = 0; i < 4; i++) {
                float4 v = bR[i];
                __nv_bfloat16 h0 = __float2bfloat16(v.x), h1 = __float2bfloat16(v.y);
                __nv_bfloat16 h2 = __float2bfloat16(v.z), h3 = __float2bfloat16(v.w);
                __nv_bfloat16 l0 = __float2bfloat16(v.x - __bfloat162float(h0));
                __nv_bfloat16 l1 = __float2bfloat16(v.y - __bfloat162float(h1));
                __nv_bfloat16 l2 = __float2bfloat16(v.z - __bfloat162float(h2));
                __nv_bfloat16 l3 = __float2bfloat16(v.w - __bfloat162float(h3));
                uint32_t off = (uint32_t)(r * ROWB + (kq + 4 * i) * 2);
                *(unsigned long long*)(Bhi + off) = pk4(h0, h1, h2, h3);
                *(unsigned long long*)(Blo + off) = pk4(l0, l1, l2, l3);
            }
        } else {
            int k = t >> 3, nb0 = (t & 7) * (NT / 8);
            #pragma unroll
            for (int i = 0; i < NT / 32; i++) {
                float vv[4] = {bR[i].x, bR[i].y, bR[i].z, bR[i].w};
                #pragma unroll
                for (int j = 0; j < 4; j++) {
                    int n = nb0 + 4 * i + j;
                    __nv_bfloat16 h = __float2bfloat16(vv[j]);
                    __nv_bfloat16 l = __float2bfloat16(vv[j] - __bfloat162float(h));
                    *(__nv_bfloat16*)(Bhi + n * ROWB + k * 2) = h;
                    *(__nv_bfloat16*)(Blo + n * ROWB + k * 2) = l;
                }
            }
        }
    };

    ldg_blk(0);
    for (int blk = 0; blk < NB; blk++) {
        sts_blk();
        __syncthreads();
        if (blk + 1 < NB) ldg_blk(blk + 1);

        #pragma unroll
        for (int ks = 0; ks < 32; ks += 16) {
            uint32_t ah[MF][4], al[MF][4], bh2[NF][2], bl2[NF][2];
            #pragma unroll
            for (int i = 0; i < MF; i++) {
                int r0 = wm_base + i * 16 + g;
                int c0 = ks + 2 * cc;
                ah[i][0] = lds32(Ahi, r0,     c0);
                ah[i][1] = lds32(Ahi, r0 + 8, c0);
                ah[i][2] = lds32(Ahi, r0,     c0 + 8);
                ah[i][3] = lds32(Ahi, r0 + 8, c0 + 8);
                al[i][0] = lds32(Alo, r0,     c0);
                al[i][1] = lds32(Alo, r0 + 8, c0);
                al[i][2] = lds32(Alo, r0,     c0 + 8);
                al[i][3] = lds32(Alo, r0 + 8, c0 + 8);
            }
            #pragma unroll
            for (int j = 0; j < NF; j++) {
                int n = wn_base + j * 8 + g;
                int c0 = ks + 2 * cc;
                bh2[j][0] = lds32(Bhi, n, c0);
                bh2[j][1] = lds32(Bhi, n, c0 + 8);
                bl2[j][0] = lds32(Blo, n, c0);
                bl2[j][1] = lds32(Blo, n, c0 + 8);
            }
            #pragma unroll
            for (int i = 0; i < MF; i++)
                #pragma unroll
                for (int j = 0; j < NF; j++) {
                    mma16816(acc[i][j], ah[i], bh2[j]);
                    mma16816(acc[i][j], ah[i], bl2[j]);
                    mma16816(acc[i][j], al[i], bh2[j]);
                }
        }
        __syncthreads();
    }

    #pragma unroll
    for (int i = 0; i < MF; i++) {
        #pragma unroll
        for (int j = 0; j < NF; j++) {
            int col = bn + wn_base + j * 8 + 2 * cc;
            #pragma unroll
            for (int h = 0; h < 2; h++) {
                int row = bm + wm_base + i * 16 + g + 8 * h;
                float2 v;
                v.x = alpha * acc[i][j][2 * h + 0];
                v.y = alpha * acc[i][j][2 * h + 1];
                if (bias) { v.x += bias[col]; v.y += bias[col + 1]; }
                if (relu) { v.x = fmaxf(v.x, 0.f); v.y = fmaxf(v.y, 0.f); }
                if (res) {
                    const float2 r2 = *(const float2*)(res + (long)row * ldc + col);
                    v.x += r2.x; v.y += r2.y;
                }
                *(float2*)(C + (long)row * ldc + col) = v;
            }
        }
    }
}

// ---------------------------------------------------------------------------
// Block reduce helper
// ---------------------------------------------------------------------------
__device__ __forceinline__ float blockReduceSum(float v) {
    __shared__ float sh[32];
    int lane = threadIdx.x & 31;
    int wid  = threadIdx.x >> 5;
    #pragma unroll
    for (int o = 16; o; o >>= 1) v += __shfl_down_sync(0xffffffffu, v, o);
    if (lane == 0) sh[wid] = v;
    __syncthreads();
    int nw = blockDim.x >> 5;
    v = (threadIdx.x < nw) ? sh[threadIdx.x] : 0.f;
    if (wid == 0) {
        #pragma unroll
        for (int o = 16; o; o >>= 1) v += __shfl_down_sync(0xffffffffu, v, o);
        if (lane == 0) sh[0] = v;
    }
    __syncthreads();
    float r = sh[0];
    __syncthreads();
    return r;
}

// ---------------------------------------------------------------------------
// LayerNorm
// ---------------------------------------------------------------------------
__global__ __launch_bounds__(256)
void ln_k(const float* __restrict__ x, const float* __restrict__ ab,
          float* __restrict__ y)
{
    long row = blockIdx.x;
    const float* xr = x + row * DD;
    float v[4]; float s = 0.f;
    #pragma unroll
    for (int i = 0; i < 4; i++) { v[i] = xr[threadIdx.x + i * 256]; s += v[i]; }
    float mean = blockReduceSum(s) * (1.0f / DD);
    float s2 = 0.f;
    #pragma unroll
    for (int i = 0; i < 4; i++) { float d = v[i] - mean; s2 += d * d; }
    float var = blockReduceSum(s2) * (1.0f / (DD - 1));
    float inv = 1.0f / (sqrtf(var) + LN_EPS);
    #pragma unroll
    for (int i = 0; i < 4; i++) {
        int d = threadIdx.x + i * 256;
        y[row * DD + d] = ab[d] * (v[i] - mean) * inv + ab[DD + d];
    }
}

// ---------------------------------------------------------------------------
// Row softmax (512 elems, warp per row)
// ---------------------------------------------------------------------------
__global__ __launch_bounds__(256)
void softmax_k(float* __restrict__ s, int rows)
{
    int gw   = (blockIdx.x * blockDim.x + threadIdx.x) >> 5;
    int lane = threadIdx.x & 31;
    if (gw >= rows) return;
    float* r = s + (long)gw * SS;
    float v[16]; float mx = -3.4e38f;
    #pragma unroll
    for (int i = 0; i < 16; i++) { v[i] = r[lane + (i << 5)]; mx = fmaxf(mx, v[i]); }
    #pragma unroll
    for (int o = 16; o; o >>= 1) mx = fmaxf(mx, __shfl_xor_sync(0xffffffffu, mx, o));
    float sum = 0.f;
    #pragma unroll
    for (int i = 0; i < 16; i++) { v[i] = expf(v[i] - mx); sum += v[i]; }
    #pragma unroll
    for (int o = 16; o; o >>= 1) sum += __shfl_xor_sync(0xffffffffu, sum, o);
    float inv = 1.0f / sum;
    #pragma unroll
    for (int i = 0; i < 16; i++) r[lane + (i << 5)] = v[i] * inv;
}

// ---------------------------------------------------------------------------
// VQ kernels
// ---------------------------------------------------------------------------
__global__ void embn_k(const float* __restrict__ emb, float* __restrict__ embn)
{
    int c = blockIdx.x;
    float e = emb[c * VQD + threadIdx.x];
    float s = e * e;
    #pragma unroll
    for (int o = 16; o; o >>= 1) s += __shfl_down_sync(0xffffffffu, s, o);
    __shared__ float sh[2];
    if ((threadIdx.x & 31) == 0) sh[threadIdx.x >> 5] = s;
    __syncthreads();
    if (threadIdx.x == 0) embn[c] = sh[0] + sh[1];
}

__global__ __launch_bounds__(128)
void vq_k(const float* __restrict__ eout, const float* __restrict__ emb,
          const float* __restrict__ embn, float* __restrict__ vq,
          float* __restrict__ rowloss)
{
    int r  = blockIdx.x;
    int sb = r & 7;
    int d  = (r >> 3) & (DD - 1);
    int b  = r >> 13;
    __shared__ float v[VQD];
    __shared__ float sd[128];
    __shared__ int   si[128];
    int t = threadIdx.x;

    if (t < VQD)
        v[t] = eout[((long)(b * SS + sb * VQD + t)) * DD + d];
    __syncthreads();

    float bd = 3.4e38f; int bi = 0x7fffffff;
    for (int c = t; c < VQN; c += 128) {
        const float* e = emb + c * VQD;
        float dot = 0.f;
        #pragma unroll
        for (int j = 0; j < VQD; j++) dot = fmaf(e[j], v[j], dot);
        float dist = embn[c] - 2.0f * dot;
        if (dist < bd) { bd = dist; bi = c; }
    }
    sd[t] = bd; si[t] = bi;
    __syncthreads();
    #pragma unroll
    for (int s = 64; s; s >>= 1) {
        if (t < s) {
            float d2 = sd[t + s]; int i2 = si[t + s];
            if (d2 < sd[t] || (d2 == sd[t] && i2 < si[t])) { sd[t] = d2; si[t] = i2; }
        }
        __syncthreads();
    }
    int best = si[0];

    float part = 0.f;
    if (t < VQD) {
        float q  = emb[best * VQD + t];
        vq[((long)(b * SS + sb * VQD + t)) * DD + d] = q;
        float df = q - v[t];
        part = df * df;
    }
    float rs = blockReduceSum(part);
    if (t == 0) rowloss[r] = rs;
}

__global__ __launch_bounds__(256)
void lossred_k(const float* __restrict__ rl, float* __restrict__ out)
{
    float s = 0.f;
    for (int i = threadIdx.x; i < NROWS_VQ; i += 256) s += rl[i];
    s = blockReduceSum(s);
    if (threadIdx.x == 0) *out = 0.25f * s * (1.0f / (float)(MT * DD));
}

// ---------------------------------------------------------------------------
// Host launch helpers
// ---------------------------------------------------------------------------
static void gemm32(const float* A, const float* B, const float* bias,
                   const float* res, float* C,
                   int M, int N, int K, int lda, int ldb, int ldc,
                   bool tb, int batch, int Hdim,
                   long sAb, long sAh, long sBb, long sBh,
                   long sCb, long sCh, long sBias,
                   float alpha, bool relu)
{
    dim3 grid((N + 127) / 128, M / 128, batch);
    if (tb)
        gemm_f32<true><<<grid, 256>>>(A, B, bias, res, C, M, N, K, lda, ldb, ldc,
                                      Hdim, sAb, sAh, sBb, sBh, sCb, sCh, sBias,
                                      alpha, relu ? 1 : 0);
    else
        gemm_f32<false><<<grid, 256>>>(A, B, bias, res, C, M, N, K, lda, ldb, ldc,
                                       Hdim, sAb, sAh, sBb, sBh, sCb, sCh, sBias,
                                       alpha, relu ? 1 : 0);
}

static void gemmMMA(const float* A, const float* B, const float* bias,
                    const float* res, float* C,
                    int M, int N, int K, int lda, int ldb, int ldc,
                    bool bnmajor, int batch, int Hdim,
                    long sAb, long sAh, long sBb, long sBh,
                    long sCb, long sCh, long sBias,
                    float alpha, bool relu)
{
    int NT = (N % 128 == 0) ? 128 : 64;
    dim3 grid(N / NT, M / 128, batch);
    size_t smem = 20480 + (size_t)NT * 160;
    int rl = relu ? 1 : 0;
    if (NT == 128) {
        if (bnmajor)
            gemm_mma<128, true><<<grid, 256, smem>>>(A, B, bias, res, C,
                K, lda, ldb, ldc, Hdim, sAb, sAh, sBb, sBh, sCb, sCh, sBias, alpha, rl);
        else
            gemm_mma<128, false><<<grid, 256, smem>>>(A, B, bias, res, C,
                K, lda, ldb, ldc, Hdim, sAb, sAh, sBb, sBh, sCb, sCh, sBias, alpha, rl);
    } else {
        gemm_mma<64, true><<<grid, 256, smem>>>(A, B, bias, res, C,
            K, lda, ldb, ldc, Hdim, sAb, sAh, sBb, sBh, sCb, sCh, sBias, alpha, rl);
    }
}

// Encoder attention: fp32 engine
static void attention32(float* qkv, float* scores, float* attno)
{
    const long SD  = (long)SS * DD;
    const long SSQ = (long)SS * SS;
    gemm32(qkv, qkv + (long)MT * DD, nullptr, nullptr, scores,
           SS, SS, DK, DD, DD, SS,
           true, BB * HEADS, HEADS,
           SD, DK, SD, DK,
           (long)HEADS * SSQ, SSQ, 0,
           0.125f, false);
    int rows = BB * HEADS * SS;
    softmax_k<<<(rows * 32 + 255) / 256, 256>>>(scores, rows);
    gemm32(scores, qkv + 2L * MT * DD, nullptr, nullptr, attno,
           SS, DK, SS, SS, DD, DD,
           false, BB * HEADS, HEADS,
           (long)HEADS * SSQ, SSQ, SD, DK,
           SD, DK, 0,
           1.0f, false);
}

// Decoder attention: HMMA engine
static void attentionMMA(float* qkv, float* scores, float* attno)
{
    const long SD  = (long)SS * DD;
    const long SSQ = (long)SS * SS;
    gemmMMA(qkv, qkv + (long)MT * DD, nullptr, nullptr, scores,
            SS, SS, DK, DD, DD, SS,
            false, BB * HEADS, HEADS,
            SD, DK, SD, DK,
            (long)HEADS * SSQ, SSQ, 0,
            0.125f, false);
    int rows = BB * HEADS * SS;
    softmax_k<<<(rows * 32 + 255) / 256, 256>>>(scores, rows);
    gemmMMA(scores, qkv + 2L * MT * DD, nullptr, nullptr, attno,
            SS, DK, SS, SS, DD, DD,
            true, BB * HEADS, HEADS,
            (long)HEADS * SSQ, SSQ, SD, DK,
            SD, DK, 0,
            1.0f, false);
}

extern "C" void kernel_launch(void* const* d_in, const int* in_sizes, int n_in,
                              void* d_out, int out_size)
{
    const float* src       = (const float*)d_in[0];
    const float* trg       = (const float*)d_in[1];
    const float* enc_ln    = (const float*)d_in[2];
    const float* enc_aw    = (const float*)d_in[3];
    const float* enc_ab    = (const float*)d_in[4];
    const float* enc_w1    = (const float*)d_in[5];
    const float* enc_b1    = (const float*)d_in[6];
    const float* enc_w2    = (const float*)d_in[7];
    const float* enc_b2    = (const float*)d_in[8];
    const float* enc_fnorm = (const float*)d_in[9];
    const float* dec_ln    = (const float*)d_in[10];
    const float* a1w       = (const float*)d_in[11];
    const float* a1b       = (const float*)d_in[12];
    const float* a2w       = (const float*)d_in[13];
    const float* a2b       = (const float*)d_in[14];
    const float* dw1       = (const float*)d_in[15];
    const float* db1       = (const float*)d_in[16];
    const float* dw2       = (const float*)d_in[17];
    const float* db2       = (const float*)d_in[18];
    const float* dec_fnorm = (const float*)d_in[19];
    const float* out_w     = (const float*)d_in[20];
    const float* out_b     = (const float*)d_in[21];
    const float* vq_emb    = (const float*)d_in[22];

    float *x, *x2, *qkv, *attno, *ffh, *scores, *eout, *vq, *embn, *rowloss;
    cudaGetSymbolAddress((void**)&x,       g_x);
    cudaGetSymbolAddress((void**)&x2,      g_x2);
    cudaGetSymbolAddress((void**)&qkv,     g_qkv);
    cudaGetSymbolAddress((void**)&attno,   g_attno);
    cudaGetSymbolAddress((void**)&ffh,     g_ffh);
    cudaGetSymbolAddress((void**)&scores,  g_scores);
    cudaGetSymbolAddress((void**)&eout,    g_eout);
    cudaGetSymbolAddress((void**)&vq,      g_vq);
    cudaGetSymbolAddress((void**)&embn,    g_embn);
    cudaGetSymbolAddress((void**)&rowloss, g_rowloss);

    const long DDL = (long)DD * DD;
    const long MTD = (long)MT * DD;

    // ---------------- Encoder: fp32 engine (feeds VQ argmin) ----------------
    cudaMemcpyAsync(x, src, MTD * sizeof(float), cudaMemcpyDeviceToDevice);
    for (int l = 0; l < NL; l++) {
        ln_k<<<MT, 256>>>(x, enc_ln + (long)((l * 2 + 0) * 2) * DD, x2);
        gemm32(x2, enc_aw + (long)l * 4 * DDL, enc_ab + (long)l * 4 * DD, nullptr, qkv,
               MT, DD, DD, DD, DD, DD,
               false, 3, 1, 0, 0, DDL, 0, MTD, 0, DD, 1.0f, false);
        attention32(qkv, scores, attno);
        gemm32(attno, enc_aw + (long)l * 4 * DDL + 3 * DDL,
               enc_ab + (long)l * 4 * DD + 3 * DD, x, x,
               MT, DD, DD, DD, DD, DD,
               false, 1, 1, 0, 0, 0, 0, 0, 0, 0, 1.0f, false);
        ln_k<<<MT, 256>>>(x, enc_ln + (long)((l * 2 + 1) * 2) * DD, x2);
        gemm32(x2, enc_w1 + (long)l * DD * DFF, enc_b1 + (long)l * DFF, nullptr, ffh,
               MT, DFF, DD, DD, DFF, DFF,
               false, 1, 1, 0, 0, 0, 0, 0, 0, 0, 1.0f, true);
        gemm32(ffh, enc_w2 + (long)l * DFF * DD, enc_b2 + (long)l * DD, x, x,
               MT, DD, DFF, DFF, DD, DD,
               false, 1, 1, 0, 0, 0, 0, 0, 0, 0, 1.0f, false);
    }
    ln_k<<<MT, 256>>>(x, enc_fnorm, eout);

    // ---------------- VQ ----------------
    embn_k<<<VQN, 64>>>(vq_emb, embn);
    vq_k<<<NROWS_VQ, 128>>>(eout, vq_emb, embn, vq, rowloss);

    // ---------------- Decoder: HMMA SPLIT=2 engine ----------------
    cudaMemcpyAsync(x, trg, MTD * sizeof(float), cudaMemcpyDeviceToDevice);
    for (int l = 0; l < NL; l++) {
        ln_k<<<MT, 256>>>(x, dec_ln + (long)((l * 3 + 0) * 2) * DD, x2);
        gemmMMA(x2, a1w + (long)l * 4 * DDL, a1b + (long)l * 4 * DD, nullptr, qkv,
                MT, DD, DD, DD, DD, DD,
                true, 3, 1, 0, 0, DDL, 0, MTD, 0, DD, 1.0f, false);
        attentionMMA(qkv, scores, attno);
        gemmMMA(attno, a1w + (long)l * 4 * DDL + 3 * DDL,
                a1b + (long)l * 4 * DD + 3 * DD, x, x,
                MT, DD, DD, DD, DD, DD,
                true, 1, 1, 0, 0, 0, 0, 0, 0, 0, 1.0f, false);
        ln_k<<<MT, 256>>>(x, dec_ln + (long)((l * 3 + 1) * 2) * DD, x2);
        gemmMMA(x2, a2w + (long)l * 4 * DDL, a2b + (long)l * 4 * DD, nullptr, qkv,
                MT, DD, DD, DD, DD, DD,
                true, 1, 1, 0, 0, 0, 0, 0, 0, 0, 1.0f, false);
        gemmMMA(vq, a2w + (long)l * 4 * DDL + DDL, a2b + (long)l * 4 * DD + DD,
                nullptr, qkv + MTD,
                MT, DD, DD, DD, DD, DD,
                true, 2, 1, 0, 0, DDL, 0, MTD, 0, DD, 1.0f, false);
        attentionMMA(qkv, scores, attno);
        gemmMMA(attno, a2w + (long)l * 4 * DDL + 3 * DDL,
                a2b + (long)l * 4 * DD + 3 * DD, x, x,
                MT, DD, DD, DD, DD, DD,
                true, 1, 1, 0, 0, 0, 0, 0, 0, 0, 1.0f, false);
        ln_k<<<MT, 256>>>(x, dec_ln + (long)((l * 3 + 2) * 2) * DD, x2);
        gemmMMA(x2, dw1 + (long)l * DD * DFF, db1 + (long)l * DFF, nullptr, ffh,
                MT, DFF, DD, DD, DFF, DFF,
                true, 1, 1, 0, 0, 0, 0, 0, 0, 0, 1.0f, true);
        gemmMMA(ffh, dw2 + (long)l * DFF * DD, db2 + (long)l * DD, x, x,
                MT, DD, DFF, DFF, DD, DD,
                true, 1, 1, 0, 0, 0, 0, 0, 0, 0, 1.0f, false);
    }
    ln_k<<<MT, 256>>>(x, dec_fnorm, x2);

    // ---------------- Output head (HMMA) + packed outputs ----------------
    float* outp = (float*)d_out;
    gemmMMA(x2, out_w, out_b, nullptr, outp,
            MT, DD, DD, DD, DD, DD,
            true, 1, 1, 0, 0, 0, 0, 0, 0, 0, 1.0f, false);

    const long M1 = MTD;
    if ((long)out_size >= 3 * M1 + 1) {
        cudaMemcpyAsync(outp + M1,     eout, M1 * sizeof(float), cudaMemcpyDeviceToDevice);
        cudaMemcpyAsync(outp + 2 * M1, vq,   M1 * sizeof(float), cudaMemcpyDeviceToDevice);
        lossred_k<<<1, 256>>>(rowloss, outp + 3 * M1);
    }
}